// round 11
// baseline (speedup 1.0000x reference)
#include <cuda_runtime.h>
#include <cuda_fp16.h>
#include <cuda_bf16.h>

// Synapse_66400194396810: out[m,n] = tanh( w2 . tanh( w1 @ (A[m,n], pre[n], post[m]) + b1 ) + b2 )
// M = N = 4096, Nh = 8.
// R11: MUFU floor = 72 MUFU-cyc / 32 elems -> ~39.6us kernel (verified R3-R8).
//      R10 showed in-kernel staging via SMEM+barrier costs +2.9us (prologue serialization).
//      This round: single launch, barrier-free weight staging -- every thread __ldg's the
//      41 weights (uniform -> broadcast) AFTER front-batching the four A-chunk DRAM loads,
//      so weight latency hides inside the A-load wait. Target bench ~= 39.6 + 2.5 (replay).

#define NH 8
#define COLS 4096

__device__ __forceinline__ float htanh(float x) {
    float y;
    asm("tanh.approx.f32 %0, %1;" : "=f"(y) : "f"(x));
    return y;
}
__device__ __forceinline__ __half2 htanh2(__half2 x) {
    unsigned yi;
    asm("tanh.approx.f16x2 %0, %1;" : "=r"(yi) : "r"(*(unsigned*)&x));
    return *(__half2*)&yi;
}

__global__ void __launch_bounds__(256) synapse_kernel(
    const float* __restrict__ A,
    const float* __restrict__ pre,
    const float* __restrict__ post,
    const float* __restrict__ w1,
    const float* __restrict__ b1,
    const float* __restrict__ w2,
    const float* __restrict__ b2,
    float* __restrict__ out)
{
    const int tid = threadIdx.x;
    const int row = blockIdx.x;
    const long long base = (long long)row * COLS;

    // --- Front-batch ALL DRAM loads first (A: 4 independent float4, MLP_p1=4). ---
    float4 a4[4];
#pragma unroll
    for (int j = 0; j < 4; j++)
        a4[j] = *reinterpret_cast<const float4*>(A + base + (j * 256 + tid) * 4);
    const float pm = __ldg(&post[row]);

    // pre is L2/L1-hot (same 16KB read by every block); issue now, resolves under A-wait.
    float4 p4[4];
#pragma unroll
    for (int j = 0; j < 4; j++)
        p4[j] = *reinterpret_cast<const float4*>(pre + (j * 256 + tid) * 4);

    // --- Barrier-free weight staging: uniform __ldg broadcasts + single-instr F2FP packs.
    //     Latency hidden inside the A-load scoreboard wait; no SMEM, no __syncthreads. ---
    const __half2 pm2 = __float2half2_rn(pm);
    __half2 W0[NH], W1h[NH], W2h[NH], CH[NH];
#pragma unroll
    for (int h = 0; h < NH; h++) {
        W0[h]  = __float2half2_rn(__ldg(&w1[h * 3 + 0]));
        W1h[h] = __float2half2_rn(__ldg(&w1[h * 3 + 1]));
        W2h[h] = __float2half2_rn(__ldg(&w2[h]));
        CH[h]  = __hfma2(__float2half2_rn(__ldg(&w1[h * 3 + 2])), pm2,
                         __float2half2_rn(__ldg(&b1[h])));
    }
    const __half2 bias2 = __float2half2_rn(__ldg(&b2[0]));

    // --- Compute 16 elems/thread: 4 coalesced float4 chunks across the row. ---
#pragma unroll
    for (int j = 0; j < 4; j++) {
        const __half2 a2lo = __floats2half2_rn(a4[j].x, a4[j].y);
        const __half2 a2hi = __floats2half2_rn(a4[j].z, a4[j].w);
        const __half2 p2lo = __floats2half2_rn(p4[j].x, p4[j].y);
        const __half2 p2hi = __floats2half2_rn(p4[j].z, p4[j].w);

        __half2 acc_lo = bias2;
        __half2 acc_hi = bias2;
#pragma unroll
        for (int h = 0; h < NH; h++) {
            __half2 zlo = __hfma2(W0[h], a2lo, __hfma2(W1h[h], p2lo, CH[h]));
            __half2 zhi = __hfma2(W0[h], a2hi, __hfma2(W1h[h], p2hi, CH[h]));
            acc_lo = __hfma2(W2h[h], htanh2(zlo), acc_lo);
            acc_hi = __hfma2(W2h[h], htanh2(zhi), acc_hi);
        }
        const float2 flo = __half22float2(acc_lo);
        const float2 fhi = __half22float2(acc_hi);
        float4 o;
        o.x = htanh(flo.x);   // final tanh in fp32 (accuracy headroom)
        o.y = htanh(flo.y);
        o.z = htanh(fhi.x);
        o.w = htanh(fhi.y);
        *reinterpret_cast<float4*>(out + base + (j * 256 + tid) * 4) = o;
    }
}

extern "C" void kernel_launch(void* const* d_in, const int* in_sizes, int n_in,
                              void* d_out, int out_size) {
    const float* A    = (const float*)d_in[0];
    const float* pre  = (const float*)d_in[1];
    const float* post = (const float*)d_in[2];
    const float* w1   = (const float*)d_in[3];
    const float* b1   = (const float*)d_in[4];
    const float* w2   = (const float*)d_in[5];
    const float* b2   = (const float*)d_in[6];
    float* out = (float*)d_out;

    const int M = out_size / COLS;   // 4096 rows, one block per row
    synapse_kernel<<<M, 256>>>(A, pre, post, w1, b1, w2, b2, out);
}